// round 6
// baseline (speedup 1.0000x reference)
#include <cuda_runtime.h>

#define B     2
#define NQ    900
#define HW    256      // 16*16 argmax domain
#define E     256      // embed dim
#define NH    8        // heads
#define MAXD2 451      // dx^2+dy^2, dx,dy in [-15,15] -> max 450
#define GRID  148      // <= SM count (B300:148, GB300:152) -> all co-resident
#define NT    256

// Persistent scratch (no allocations allowed). SELF-CLEANING: every field is
// returned to zero before kernel exit, so graph replays are deterministic.
// First run relies on static zero-init.
__device__ unsigned char g_cell[B * NQ];    // argmax cell per (b,q)
__device__ int           g_cnt[B * HW];     // cell histogram per batch
__device__ int           g_p[B * MAXD2];    // pair-count histogram (EXACT int)
__device__ float         g_lut[B * MAXD2];  // bias_mean vs integer d2
__device__ unsigned int  g_sync[4];         // grid-barrier counters

// Software grid barrier. Safe because grid (148) <= SM count: every block is
// resident in wave 1, so spinning cannot deadlock.
__device__ __forceinline__ void grid_bar(unsigned int* c) {
    __syncthreads();
    if (threadIdx.x == 0) {
        __threadfence();                    // release: publish my block's writes
        atomicAdd(c, 1u);
        while (*(volatile unsigned int*)c < (unsigned int)GRID) __nanosleep(64);
        __threadfence();                    // acquire
    }
    __syncthreads();
}

__global__ void __launch_bounds__(NT) k_topo(
    const float* __restrict__ rp,   const float* __restrict__ attn,
    const float* __restrict__ lam,
    const float* __restrict__ w1,   const float* __restrict__ b1,
    const float* __restrict__ w2,   const float* __restrict__ b2,
    float* __restrict__ out)
{
    __shared__ int    sCnt[B * HW];
    __shared__ int    sP[B * MAXD2];
    __shared__ double sRed[NT];
    __shared__ float  sMean[B];
    __shared__ float  sLut[B * MAXD2];

    const int t    = threadIdx.x;
    const int bid  = blockIdx.x;
    const int wid  = t >> 5;
    const int lane = t & 31;
    const int gwarp = bid * 8 + wid;            // 0..1183

    // ---------------- Phase A: argmax (1-2 queries per warp) ----------------
    // float4 loads; in-lane ascending index + '>' keeps FIRST max (jnp.argmax).
    for (int q = gwarp; q < B * NQ; q += GRID * 8) {
        const float4* p4 = (const float4*)(rp + (size_t)q * HW);
        float4 va = p4[lane];
        float4 vb = p4[lane + 32];
        float v[8] = {va.x, va.y, va.z, va.w, vb.x, vb.y, vb.z, vb.w};
        float best = -__int_as_float(0x7f800000);
        int   bi   = 0;
        #pragma unroll
        for (int k = 0; k < 8; k++) {
            int i = (k < 4) ? (4 * lane + k) : (128 + 4 * lane + (k - 4));
            if (v[k] > best) { best = v[k]; bi = i; }
        }
        #pragma unroll
        for (int off = 16; off; off >>= 1) {
            float ov = __shfl_down_sync(0xffffffffu, best, off);
            int   oi = __shfl_down_sync(0xffffffffu, bi,   off);
            if (ov > best || (ov == best && oi < bi)) { best = ov; bi = oi; }
        }
        if (lane == 0) {
            g_cell[q] = (unsigned char)bi;
            atomicAdd(&g_cnt[(q >= NQ ? HW : 0) + bi], 1);
        }
    }
    // zero the block-private pair hist while other blocks finish argmax
    for (int i = t; i < B * MAXD2; i += NT) sP[i] = 0;

    grid_bar(&g_sync[0]);

    // ---------------- Phase C: distributed pair-count histogram -------------
    // combo = (b, cell k); thread t = cell l. All-integer -> exact.
    sCnt[t]       = g_cnt[t];
    sCnt[t + 256] = g_cnt[t + 256];
    __syncthreads();
    for (int combo = bid; combo < B * HW; combo += GRID) {
        int b  = combo >> 8;
        int k  = combo & 255;
        int ck = sCnt[(b << 8) + k];
        int cl = sCnt[(b << 8) + t];
        if (ck && cl) {
            int dx = (k & 15) - (t & 15);
            int dy = (k >> 4) - (t >> 4);
            atomicAdd(&sP[b * MAXD2 + dx * dx + dy * dy], ck * cl);
        }
    }
    __syncthreads();
    for (int i = t; i < B * MAXD2; i += NT) {
        int v = sP[i];
        if (v) atomicAdd(&g_p[i], v);
    }

    grid_bar(&g_sync[1]);

    // ------- Phase D: per-batch mean (redundant per block, deterministic:
    //         identical code + identical global ints -> identical fp64) -------
    if (bid == 0) { g_cnt[t] = 0; g_cnt[t + 256] = 0; }   // self-clean (last read was Phase C)
    for (int b = 0; b < B; b++) {
        double acc = (double)g_p[b * MAXD2 + t] * (double)sqrtf((float)t);
        if (t + 256 < MAXD2)
            acc += (double)g_p[b * MAXD2 + t + 256] * (double)sqrtf((float)(t + 256));
        sRed[t] = acc;
        __syncthreads();
        for (int s = 128; s; s >>= 1) {
            if (t < s) sRed[t] += sRed[t + s];
            __syncthreads();
        }
        if (t == 0)
            sMean[b] = (float)(sRed[0] / 15.0 / ((double)NQ * (double)NQ));
        __syncthreads();
    }

    // ---------------- Phase E: LUT, one warp per entry (902 <= 1184) --------
    if (gwarp < B * MAXD2) {
        int   b   = gwarp >= MAXD2 ? 1 : 0;
        int   d2  = gwarp - b * MAXD2;
        float dst = sqrtf((float)d2) * (1.0f / 15.0f);
        float tt  = dst / (sMean[b] + 1e-6f);

        float acc = 0.f;
        #pragma unroll
        for (int k = 0; k < 8; k++) {
            int i = lane + k * 32;
            const float4* w2r = (const float4*)(w2 + i * NH);
            float4 wa = w2r[0], wb = w2r[1];
            float ws = ((wa.x + wa.y) + (wa.z + wa.w) +
                        (wb.x + wb.y) + (wb.z + wb.w)) * (1.0f / NH);
            acc = fmaf(fmaxf(fmaf(tt, w1[i], b1[i]), 0.f), ws, acc);
        }
        #pragma unroll
        for (int off = 16; off; off >>= 1)
            acc += __shfl_down_sync(0xffffffffu, acc, off);
        if (lane == 0) {
            float bm = 0.f;
            #pragma unroll
            for (int h = 0; h < NH; h++) bm += b2[h];
            g_lut[gwarp] = acc + bm * (1.0f / NH);
        }
    }

    grid_bar(&g_sync[2]);

    // ---------------- stage LUT (both batches) + self-clean g_p -------------
    for (int i = t; i < B * MAXD2; i += NT) sLut[i] = g_lut[i];
    if (bid == 1)
        for (int i = t; i < B * MAXD2; i += NT) g_p[i] = 0;  // last read was Phase D
    __syncthreads();

    // ---------------- Phase F: out = attn + lam * lut[d2(ci,cj)] ------------
    // ~12-13 rows per block; cj depends only on (batch, column) -> hoisted.
    const float la  = __ldg(lam);
    const bool  act = t < NQ / 4;               // 225 float4 per row
    int cjx[2][4], cjy[2][4];
    if (act) {
        #pragma unroll
        for (int b = 0; b < B; b++) {
            uchar4 c4 = *(const uchar4*)(g_cell + b * NQ + t * 4);
            unsigned char cc[4] = {c4.x, c4.y, c4.z, c4.w};
            #pragma unroll
            for (int k = 0; k < 4; k++) { cjx[b][k] = cc[k] & 15; cjy[b][k] = cc[k] >> 4; }
        }
    }
    for (int row = bid; row < B * NQ; row += GRID) {
        if (!act) continue;
        int b   = row >= NQ ? 1 : 0;
        int ci  = g_cell[row];                  // uniform per (block, iter)
        int cix = ci & 15, ciy = ci >> 4;
        const float* lutb = sLut + b * MAXD2;

        const float4* arow = (const float4*)(attn + (size_t)row * NQ);
        float4 a = __ldcs(arow + t);
        float av[4] = {a.x, a.y, a.z, a.w};
        float r[4];
        #pragma unroll
        for (int k = 0; k < 4; k++) {
            int dx = cix - cjx[b][k];
            int dy = ciy - cjy[b][k];
            r[k] = fmaf(la, lutb[dx * dx + dy * dy], av[k]);
        }
        float4* orow = (float4*)(out + (size_t)row * NQ);
        __stcs(orow + t, make_float4(r[0], r[1], r[2], r[3]));
    }

    // ---------------- exit barrier + counter reset (race-free) --------------
    __syncthreads();
    if (t == 0) {
        __threadfence();
        atomicAdd(&g_sync[3], 1u);
        if (bid == 0) {
            while (*(volatile unsigned int*)&g_sync[3] < (unsigned int)GRID) __nanosleep(64);
            // every block has passed every barrier; safe to reset all counters
            g_sync[0] = 0; g_sync[1] = 0; g_sync[2] = 0; g_sync[3] = 0;
            __threadfence();
        }
    }
}

// ---------------------------------------------------------------------------
// Launch: ONE persistent kernel.
// Inputs: attn[2*900*900] f32, ref_pts[2*900*256] f32, lam[1], w1[256],
// b1[256], w2[256*8], b2[8]. Output: [2*900*900] f32.
// ---------------------------------------------------------------------------
extern "C" void kernel_launch(void* const* d_in, const int* in_sizes, int n_in,
                              void* d_out, int out_size) {
    const float* attn = (const float*)d_in[0];
    const float* rp   = (const float*)d_in[1];
    const float* lam  = (const float*)d_in[2];
    const float* w1   = (const float*)d_in[3];
    const float* b1   = (const float*)d_in[4];
    const float* w2   = (const float*)d_in[5];
    const float* b2   = (const float*)d_in[6];
    float*       out  = (float*)d_out;

    k_topo<<<GRID, NT>>>(rp, attn, lam, w1, b1, w2, b2, out);
}

// round 7
// speedup vs baseline: 1.3271x; 1.3271x over previous
#include <cuda_runtime.h>

#define B   2
#define NQ  900
#define HW  256      // 16*16 argmax domain
#define E   256      // embed dim
#define NH  8        // heads
#define MAXD2 451    // dx^2+dy^2, dx,dy in [-15,15] -> max 450

// Scratch (no allocations allowed -> __device__ globals).
// SELF-CLEANING: k_pair's last block re-zeroes g_cnt/g_p/g_ticket after use,
// so every kernel_launch invocation starts from the zero state (first run:
// static zero-init at module load).
__device__ unsigned char g_cell[B * NQ];    // argmax cell index per (b,q)
__device__ int           g_cnt[B * HW];     // cell histogram per batch
__device__ int           g_p[B * MAXD2];    // pair-count histogram over d2 (EXACT)
__device__ float         g_lut[B * MAXD2];  // bias_mean as function of integer d2
__device__ float         g_mean[B];         // per-batch mean distance
__device__ unsigned int  g_ticket;          // last-block-done counter for k_pair

#if defined(__CUDA_ARCH__) && (__CUDA_ARCH__ >= 900)
#define GRID_DEP_SYNC() cudaGridDependencySynchronize()
#else
#define GRID_DEP_SYNC()
#endif

// ---------------------------------------------------------------------------
// Kernel 1: per-(b,q) argmax over 256 values (one warp each), first-index
// tiebreak to match jnp.argmax. Builds the cell histogram. float4 loads.
// ---------------------------------------------------------------------------
__global__ void k_argmax(const float* __restrict__ rp) {
    int gw   = (blockIdx.x * blockDim.x + threadIdx.x) >> 5;
    int lane = threadIdx.x & 31;
    if (gw >= B * NQ) return;

    const float4* p4 = (const float4*)(rp + (size_t)gw * HW);
    float4 va = p4[lane];        // indices 4*lane .. 4*lane+3
    float4 vb = p4[lane + 32];   // indices 128+4*lane .. +3

    float best = -__int_as_float(0x7f800000); // -inf
    int   bi   = 0;
    float v[8] = {va.x, va.y, va.z, va.w, vb.x, vb.y, vb.z, vb.w};
    #pragma unroll
    for (int k = 0; k < 8; k++) {
        int i = (k < 4 ? 4 * lane + k : 128 + 4 * lane + (k - 4));
        if (v[k] > best) { best = v[k]; bi = i; }   // in-lane ascending -> first max
    }
    #pragma unroll
    for (int off = 16; off; off >>= 1) {
        float ov = __shfl_down_sync(0xffffffffu, best, off);
        int   oi = __shfl_down_sync(0xffffffffu, bi,   off);
        if (ov > best || (ov == best && oi < bi)) { best = ov; bi = oi; }
    }
    if (lane == 0) {
        g_cell[gw] = (unsigned char)bi;
        atomicAdd(&g_cnt[(gw / NQ) * HW + bi], 1);
    }
}

// ---------------------------------------------------------------------------
// Kernel 2: pair-count histogram over integer d2. One block per (b, cell k);
// thread l handles pair (k,l). All-integer -> exact & deterministic.
// Last block (ticket): reduces histogram into per-batch mean distance
// (fp64, fixed order), then ZEROES all scratch for the next run.
// ---------------------------------------------------------------------------
__global__ void k_pair() {
    __shared__ int    sP[MAXD2];
    __shared__ int    sCnt[HW];
    __shared__ bool   sLast;
    __shared__ double sRed[256];

    int b = blockIdx.x >> 8;
    int k = blockIdx.x & 255;
    int t = threadIdx.x;

    sP[t] = 0;
    if (t + 256 < MAXD2) sP[t + 256] = 0;

    GRID_DEP_SYNC();                    // wait for k_argmax's g_cnt

    sCnt[t] = g_cnt[b * HW + t];
    __syncthreads();

    int ck = sCnt[k];
    if (ck) {
        int cl = sCnt[t];
        if (cl) {
            int dx = (k & 15) - (t & 15);
            int dy = (k >> 4) - (t >> 4);
            atomicAdd(&sP[dx * dx + dy * dy], ck * cl);
        }
    }
    __syncthreads();

    int v = sP[t];
    if (v) atomicAdd(&g_p[b * MAXD2 + t], v);
    if (t + 256 < MAXD2) {
        v = sP[t + 256];
        if (v) atomicAdd(&g_p[b * MAXD2 + t + 256], v);
    }

    // ---- last-block-done: finalize means, then clean scratch ----
    __threadfence();
    if (t == 0)
        sLast = (atomicAdd(&g_ticket, 1u) == (unsigned)(gridDim.x - 1));
    __syncthreads();
    if (!sLast) return;

    for (int bb = 0; bb < B; bb++) {
        double acc = (double)g_p[bb * MAXD2 + t] * (double)sqrtf((float)t);
        if (t + 256 < MAXD2)
            acc += (double)g_p[bb * MAXD2 + t + 256] * (double)sqrtf((float)(t + 256));
        sRed[t] = acc;
        __syncthreads();
        for (int s = 128; s; s >>= 1) {
            if (t < s) sRed[t] += sRed[t + s];
            __syncthreads();
        }
        if (t == 0)
            g_mean[bb] = (float)(sRed[0] / 15.0 / ((double)NQ * (double)NQ));
        __syncthreads();
    }

    // self-clean for the next run
    for (int i = t; i < B * MAXD2; i += 256) g_p[i] = 0;
    g_cnt[t] = 0;
    g_cnt[t + 256] = 0;
    if (t == 0) g_ticket = 0;
}

// ---------------------------------------------------------------------------
// Kernel 3: LUT build, one warp per entry. PDL prologue computes the
// head-averaged weights from inputs only; the grid sync covers only g_mean.
//   LUT[b][d2] = sum_e relu(t*w1[e]+b1[e]) * mean_h(w2[e,h]) + mean_h(b2),
//   t = (sqrt(d2)/15) / (mean[b] + 1e-6)
// ---------------------------------------------------------------------------
__global__ void k_lut(const float* __restrict__ w1, const float* __restrict__ b1,
                      const float* __restrict__ w2, const float* __restrict__ b2) {
    int gwarp = blockIdx.x * (blockDim.x >> 5) + (threadIdx.x >> 5);
    int lane  = threadIdx.x & 31;
    if (gwarp >= B * MAXD2) return;

    // prologue (inputs only — overlaps k_pair under PDL)
    float w1r[8], b1r[8], wsr[8];
    #pragma unroll
    for (int k = 0; k < 8; k++) {
        int i = lane + k * 32;
        w1r[k] = w1[i];
        b1r[k] = b1[i];
        const float4* w2r = (const float4*)(w2 + i * NH);
        float4 wa = w2r[0], wb = w2r[1];
        wsr[k] = ((wa.x + wa.y) + (wa.z + wa.w) +
                  (wb.x + wb.y) + (wb.z + wb.w)) * (1.0f / NH);
    }
    float bm = 0.f;
    #pragma unroll
    for (int h = 0; h < NH; h++) bm += b2[h];
    bm *= (1.0f / NH);

    int   bb  = gwarp >= MAXD2 ? 1 : 0;
    int   d2  = gwarp - bb * MAXD2;
    float dst = sqrtf((float)d2) * (1.0f / 15.0f);

    GRID_DEP_SYNC();                    // wait for k_pair's g_mean

    float tt = dst / (g_mean[bb] + 1e-6f);

    float acc = 0.f;
    #pragma unroll
    for (int k = 0; k < 8; k++)
        acc = fmaf(fmaxf(fmaf(tt, w1r[k], b1r[k]), 0.f), wsr[k], acc);
    #pragma unroll
    for (int off = 16; off; off >>= 1)
        acc += __shfl_down_sync(0xffffffffu, acc, off);
    if (lane == 0) g_lut[gwarp] = acc + bm;
}

// ---------------------------------------------------------------------------
// Kernel 4: out = attn + lam * lut[d2(cell_i, cell_j)].
// 4 rows per block (450 blocks x 512 threads): thread handles rows
// row0+half and row0+2+half with BOTH float4 loads issued back-to-back
// (MLP_p1=2) in the PDL prologue, before the grid sync. Blocks never
// straddle the batch boundary (900 % 4 == 0) -> one 451-float LUT stage.
// ---------------------------------------------------------------------------
__global__ void __launch_bounds__(512) k_out(const float* __restrict__ attn,
                                             const float* __restrict__ lam,
                                             float* __restrict__ out) {
    __shared__ float sLut[MAXD2];

    int t    = threadIdx.x;
    int row0 = blockIdx.x * 4;            // rows row0 .. row0+3 (same batch)
    int b    = row0 >= NQ ? 1 : 0;
    int half = t >> 8;                    // 0/1
    int v    = t & 255;                   // vector index within row
    bool act = v < NQ / 4;                // 225 float4 per row

    int rowA = row0 + half;               // first row for this thread
    int rowB = row0 + 2 + half;           // second row

    // prologue: input-only loads, both in flight before any dependency
    float4 aA = make_float4(0.f, 0.f, 0.f, 0.f);
    float4 aB = aA;
    if (act) {
        aA = __ldcs((const float4*)(attn + (size_t)rowA * NQ) + v);
        aB = __ldcs((const float4*)(attn + (size_t)rowB * NQ) + v);
    }
    float la = __ldg(lam);

    GRID_DEP_SYNC();                      // wait for g_lut / g_cell

    if (t < MAXD2) sLut[t] = g_lut[b * MAXD2 + t];
    int ciA = g_cell[rowA];
    int ciB = g_cell[rowB];
    uchar4 cj4 = make_uchar4(0, 0, 0, 0);
    if (act) cj4 = *(const uchar4*)(g_cell + b * NQ + v * 4);
    __syncthreads();

    if (!act) return;
    int cjx[4], cjy[4];
    unsigned char cc[4] = {cj4.x, cj4.y, cj4.z, cj4.w};
    #pragma unroll
    for (int k = 0; k < 4; k++) { cjx[k] = cc[k] & 15; cjy[k] = cc[k] >> 4; }

    int cixA = ciA & 15, ciyA = ciA >> 4;
    int cixB = ciB & 15, ciyB = ciB >> 4;

    float avA[4] = {aA.x, aA.y, aA.z, aA.w};
    float avB[4] = {aB.x, aB.y, aB.z, aB.w};
    float rA[4], rB[4];
    #pragma unroll
    for (int k = 0; k < 4; k++) {
        int dxA = cixA - cjx[k], dyA = ciyA - cjy[k];
        int dxB = cixB - cjx[k], dyB = ciyB - cjy[k];
        rA[k] = fmaf(la, sLut[dxA * dxA + dyA * dyA], avA[k]);
        rB[k] = fmaf(la, sLut[dxB * dxB + dyB * dyB], avB[k]);
    }
    __stcs((float4*)(out + (size_t)rowA * NQ) + v, make_float4(rA[0], rA[1], rA[2], rA[3]));
    __stcs((float4*)(out + (size_t)rowB * NQ) + v, make_float4(rB[0], rB[1], rB[2], rB[3]));
}

// ---------------------------------------------------------------------------
// Launch: 4 kernels chained with Programmatic Dependent Launch.
// ---------------------------------------------------------------------------
static inline void pdl_cfg(cudaLaunchConfig_t* cfg, cudaLaunchAttribute* attr,
                           dim3 grid, dim3 block) {
    attr->id = cudaLaunchAttributeProgrammaticStreamSerialization;
    attr->val.programmaticStreamSerializationAllowed = 1;
    cfg->gridDim = grid;
    cfg->blockDim = block;
    cfg->dynamicSmemBytes = 0;
    cfg->stream = 0;          // legacy default stream (same as <<<>>>)
    cfg->attrs = attr;
    cfg->numAttrs = 1;
}

extern "C" void kernel_launch(void* const* d_in, const int* in_sizes, int n_in,
                              void* d_out, int out_size) {
    const float* attn = (const float*)d_in[0];
    const float* rp   = (const float*)d_in[1];
    const float* lam  = (const float*)d_in[2];
    const float* w1   = (const float*)d_in[3];
    const float* b1   = (const float*)d_in[4];
    const float* w2   = (const float*)d_in[5];
    const float* b2   = (const float*)d_in[6];
    float*       out  = (float*)d_out;

    // primary
    k_argmax<<<(B * NQ * 32) / 256, 256>>>(rp);   // 225 blocks

    cudaLaunchConfig_t cfg;
    cudaLaunchAttribute attr;

    pdl_cfg(&cfg, &attr, dim3(B * HW), dim3(256));
    cudaLaunchKernelEx(&cfg, k_pair);

    pdl_cfg(&cfg, &attr, dim3((B * MAXD2 + 7) / 8), dim3(256));
    cudaLaunchKernelEx(&cfg, k_lut, w1, b1, w2, b2);

    pdl_cfg(&cfg, &attr, dim3(B * NQ / 4), dim3(512));
    cudaLaunchKernelEx(&cfg, k_out, attn, lam, out);
}